// round 1
// baseline (speedup 1.0000x reference)
#include <cuda_runtime.h>
#include <math.h>

#define BATCH   2
#define SEQ     2048
#define DMODEL  1024
#define NHEADS  16
#define DHEAD   64
#define MTOT    (BATCH*SEQ)   // 4096

// Scratch (allocation-free rule: __device__ globals)
__device__ float g_Q[MTOT*DMODEL];
__device__ float g_K[MTOT*DMODEL];
__device__ float g_V[MTOT*DMODEL];
__device__ float g_O[MTOT*DMODEL];

// ---------------------------------------------------------------------------
// SGEMM: C[M,N] = A[M,K] * B[K,N], row-major, 128x128 block, 8x8 per thread
// ---------------------------------------------------------------------------
__global__ __launch_bounds__(256)
void sgemm128(const float* __restrict__ A, const float* __restrict__ B,
              float* __restrict__ C, int M, int N, int K)
{
    __shared__ float As[16][128];   // transposed: As[k][m]
    __shared__ float Bs[16][128];   // Bs[k][n]

    const int tid = threadIdx.x;
    const int tx  = tid & 15;       // 0..15  (N direction)
    const int ty  = tid >> 4;       // 0..15  (M direction)
    const int rowBase = blockIdx.y * 128;
    const int colBase = blockIdx.x * 128;

    float acc[8][8];
    #pragma unroll
    for (int i = 0; i < 8; i++)
        #pragma unroll
        for (int j = 0; j < 8; j++) acc[i][j] = 0.f;

    for (int k0 = 0; k0 < K; k0 += 16) {
        // A tile: 128 rows x 16 cols  (512 float4s)
        #pragma unroll
        for (int l = 0; l < 2; l++) {
            int f = tid + l * 256;
            int r = f >> 2, c = (f & 3) << 2;
            float4 a = *(const float4*)(A + (size_t)(rowBase + r) * K + k0 + c);
            As[c + 0][r] = a.x; As[c + 1][r] = a.y;
            As[c + 2][r] = a.z; As[c + 3][r] = a.w;
        }
        // B tile: 16 rows x 128 cols  (512 float4s)
        #pragma unroll
        for (int l = 0; l < 2; l++) {
            int f = tid + l * 256;
            int r = f >> 5, c = (f & 31) << 2;
            *(float4*)(&Bs[r][c]) = *(const float4*)(B + (size_t)(k0 + r) * N + colBase + c);
        }
        __syncthreads();

        #pragma unroll
        for (int kk = 0; kk < 16; kk++) {
            float ra[8], rb[8];
            #pragma unroll
            for (int i = 0; i < 4; i++) {
                ra[i]     = As[kk][ty * 4 + i];
                ra[4 + i] = As[kk][64 + ty * 4 + i];
            }
            #pragma unroll
            for (int j = 0; j < 4; j++) {
                rb[j]     = Bs[kk][tx * 4 + j];
                rb[4 + j] = Bs[kk][64 + tx * 4 + j];
            }
            #pragma unroll
            for (int i = 0; i < 8; i++)
                #pragma unroll
                for (int j = 0; j < 8; j++)
                    acc[i][j] = fmaf(ra[i], rb[j], acc[i][j]);
        }
        __syncthreads();
    }

    #pragma unroll
    for (int i = 0; i < 8; i++) {
        int r = rowBase + ((i < 4) ? (ty * 4 + i) : (64 + ty * 4 + (i - 4)));
        float4 v0 = make_float4(acc[i][0], acc[i][1], acc[i][2], acc[i][3]);
        float4 v1 = make_float4(acc[i][4], acc[i][5], acc[i][6], acc[i][7]);
        *(float4*)(C + (size_t)r * N + colBase + tx * 4)      = v0;
        *(float4*)(C + (size_t)r * N + colBase + 64 + tx * 4) = v1;
    }
}

// ---------------------------------------------------------------------------
// RoPE applied in-place to Q and K.
// Layout: [b, s, h*64 + d], rotate pairs (d, d+32) within each head.
// ---------------------------------------------------------------------------
__global__ void rope_kernel(float* __restrict__ Q, float* __restrict__ K,
                            const float* __restrict__ cosT,
                            const float* __restrict__ sinT)
{
    int idx = blockIdx.x * blockDim.x + threadIdx.x;   // [0, MTOT*NHEADS*32)
    int d  = idx & 31;
    int h  = (idx >> 5) & (NHEADS - 1);
    int ms = idx >> 9;                 // b*SEQ + s
    int s  = ms & (SEQ - 1);

    float c  = cosT[s * 32 + d];
    float sn = sinT[s * 32 + d];
    size_t base = (size_t)ms * DMODEL + h * DHEAD + d;

    float x1 = Q[base], x2 = Q[base + 32];
    Q[base]      = x1 * c - x2 * sn;
    Q[base + 32] = x2 * c + x1 * sn;

    float y1 = K[base], y2 = K[base + 32];
    K[base]      = y1 * c - y2 * sn;
    K[base + 32] = y2 * c + y1 * sn;
}

// ---------------------------------------------------------------------------
// Flash attention (fp32, causal): per block = (q-tile of 64 rows, head, batch)
// Online softmax, K/V tiles of 64 streamed; causal blocks beyond diagonal
// skipped entirely.
// Dynamic smem layout: Qs[64][64] | KSs[64][65] (K tile, reused as S/P tile)
//                      | Vs[64][65] | m[64] | l[64] | alpha[64]
// ---------------------------------------------------------------------------
__global__ __launch_bounds__(256)
void attn_kernel(const float* __restrict__ Q, const float* __restrict__ K,
                 const float* __restrict__ V, float* __restrict__ O)
{
    extern __shared__ float sm[];
    float* Qs   = sm;                  // 64*64
    float* KSs  = Qs  + 64 * 64;       // 64*65
    float* Vs   = KSs + 64 * 65;       // 64*65
    float* mrow = Vs  + 64 * 65;       // 64
    float* lrow = mrow + 64;           // 64
    float* arow = lrow + 64;           // 64

    const int qb = blockIdx.x, h = blockIdx.y, b = blockIdx.z;
    const int tid = threadIdx.x;
    const int tx = tid & 15, ty = tid >> 4;
    const int r0 = ty * 4, c0 = tx * 4;

    // Load Q tile (64 x 64)
    #pragma unroll
    for (int l = 0; l < 4; l++) {
        int f = tid + l * 256;
        int r = f >> 4, c = (f & 15) << 2;
        float4 v4 = *(const float4*)(Q + ((size_t)(b * SEQ + qb * 64 + r)) * DMODEL
                                       + h * DHEAD + c);
        Qs[r * 64 + c + 0] = v4.x; Qs[r * 64 + c + 1] = v4.y;
        Qs[r * 64 + c + 2] = v4.z; Qs[r * 64 + c + 3] = v4.w;
    }
    if (tid < 64) { mrow[tid] = -INFINITY; lrow[tid] = 0.f; }

    float acc[4][4];
    #pragma unroll
    for (int i = 0; i < 4; i++)
        #pragma unroll
        for (int j = 0; j < 4; j++) acc[i][j] = 0.f;
    __syncthreads();

    for (int kj = 0; kj <= qb; kj++) {
        // Load K and V tiles
        #pragma unroll
        for (int l = 0; l < 4; l++) {
            int f = tid + l * 256;
            int r = f >> 4, c = (f & 15) << 2;
            size_t gb = ((size_t)(b * SEQ + kj * 64 + r)) * DMODEL + h * DHEAD + c;
            float4 kv = *(const float4*)(K + gb);
            KSs[r * 65 + c + 0] = kv.x; KSs[r * 65 + c + 1] = kv.y;
            KSs[r * 65 + c + 2] = kv.z; KSs[r * 65 + c + 3] = kv.w;
            float4 vv = *(const float4*)(V + gb);
            Vs[r * 65 + c + 0] = vv.x; Vs[r * 65 + c + 1] = vv.y;
            Vs[r * 65 + c + 2] = vv.z; Vs[r * 65 + c + 3] = vv.w;
        }
        __syncthreads();

        // S = Q * K^T  (each thread: 4x4)
        float sreg[4][4];
        #pragma unroll
        for (int i = 0; i < 4; i++)
            #pragma unroll
            for (int j = 0; j < 4; j++) sreg[i][j] = 0.f;

        #pragma unroll 4
        for (int d = 0; d < 64; d++) {
            float rq[4], rk[4];
            #pragma unroll
            for (int i = 0; i < 4; i++) rq[i] = Qs[(r0 + i) * 64 + d];
            #pragma unroll
            for (int j = 0; j < 4; j++) rk[j] = KSs[(c0 + j) * 65 + d];
            #pragma unroll
            for (int i = 0; i < 4; i++)
                #pragma unroll
                for (int j = 0; j < 4; j++)
                    sreg[i][j] = fmaf(rq[i], rk[j], sreg[i][j]);
        }
        __syncthreads();   // everyone done reading K tile

        // Scale + causal mask, store S into (reused) KSs buffer
        const int qrow = qb * 64, kcol = kj * 64;
        #pragma unroll
        for (int i = 0; i < 4; i++)
            #pragma unroll
            for (int j = 0; j < 4; j++) {
                float sv = sreg[i][j] * 0.125f;               // Dh^-0.5 = 1/8
                if (kcol + c0 + j > qrow + r0 + i) sv = -1e30f;
                KSs[(r0 + i) * 65 + c0 + j] = sv;
            }
        __syncthreads();

        // Online softmax: one thread per row
        if (tid < 64) {
            int r = tid;
            float mold = mrow[r], mx = mold;
            #pragma unroll 8
            for (int j = 0; j < 64; j++) mx = fmaxf(mx, KSs[r * 65 + j]);
            float a = __expf(mold - mx);
            float sum = 0.f;
            #pragma unroll 8
            for (int j = 0; j < 64; j++) {
                float p = __expf(KSs[r * 65 + j] - mx);
                KSs[r * 65 + j] = p;
                sum += p;
            }
            mrow[r] = mx;
            lrow[r] = lrow[r] * a + sum;
            arow[r] = a;
        }
        __syncthreads();

        // Rescale accumulator and add P * V
        float al[4];
        #pragma unroll
        for (int i = 0; i < 4; i++) al[i] = arow[r0 + i];
        #pragma unroll
        for (int i = 0; i < 4; i++)
            #pragma unroll
            for (int j = 0; j < 4; j++) acc[i][j] *= al[i];

        #pragma unroll 4
        for (int kk = 0; kk < 64; kk++) {
            float rp[4], rv[4];
            #pragma unroll
            for (int i = 0; i < 4; i++) rp[i] = KSs[(r0 + i) * 65 + kk];
            #pragma unroll
            for (int j = 0; j < 4; j++) rv[j] = Vs[kk * 65 + c0 + j];
            #pragma unroll
            for (int i = 0; i < 4; i++)
                #pragma unroll
                for (int j = 0; j < 4; j++)
                    acc[i][j] = fmaf(rp[i], rv[j], acc[i][j]);
        }
        __syncthreads();   // before next iteration overwrites KSs/Vs
    }

    // Normalize and write O tile
    #pragma unroll
    for (int i = 0; i < 4; i++) {
        float inv = 1.0f / lrow[r0 + i];
        size_t base = ((size_t)(b * SEQ + qb * 64 + r0 + i)) * DMODEL + h * DHEAD;
        float4 o4 = make_float4(acc[i][0] * inv, acc[i][1] * inv,
                                acc[i][2] * inv, acc[i][3] * inv);
        *(float4*)(O + base + c0) = o4;
    }
}

// ---------------------------------------------------------------------------
// Launch
// ---------------------------------------------------------------------------
extern "C" void kernel_launch(void* const* d_in, const int* in_sizes, int n_in,
                              void* d_out, int out_size)
{
    const float* hidden = (const float*)d_in[0];
    const float* cosT   = (const float*)d_in[1];
    const float* sinT   = (const float*)d_in[2];
    // d_in[3] = attention_mask (pure causal; reproduced analytically)
    const float* Wq     = (const float*)d_in[4];
    const float* Wk     = (const float*)d_in[5];
    const float* Wv     = (const float*)d_in[6];
    const float* Wo     = (const float*)d_in[7];
    float* out = (float*)d_out;

    float *Qp, *Kp, *Vp, *Op;
    cudaGetSymbolAddress((void**)&Qp, g_Q);
    cudaGetSymbolAddress((void**)&Kp, g_K);
    cudaGetSymbolAddress((void**)&Vp, g_V);
    cudaGetSymbolAddress((void**)&Op, g_O);

    const int attn_smem = (64 * 64 + 2 * 64 * 65 + 3 * 64) * (int)sizeof(float); // 50432
    cudaFuncSetAttribute(attn_kernel, cudaFuncAttributeMaxDynamicSharedMemorySize,
                         attn_smem);

    dim3 gg(DMODEL / 128, MTOT / 128);   // (8, 32)

    sgemm128<<<gg, 256>>>(hidden, Wq, Qp, MTOT, DMODEL, DMODEL);
    sgemm128<<<gg, 256>>>(hidden, Wk, Kp, MTOT, DMODEL, DMODEL);
    sgemm128<<<gg, 256>>>(hidden, Wv, Vp, MTOT, DMODEL, DMODEL);

    rope_kernel<<<(MTOT * NHEADS * 32) / 256, 256>>>(Qp, Kp, cosT, sinT);

    attn_kernel<<<dim3(SEQ / 64, NHEADS, BATCH), 256, attn_smem>>>(Qp, Kp, Vp, Op);

    sgemm128<<<gg, 256>>>(Op, Wo, out, MTOT, DMODEL, DMODEL);
}

// round 3
// speedup vs baseline: 1.4985x; 1.4985x over previous
#include <cuda_runtime.h>
#include <math.h>

#define BATCH   2
#define SEQ     2048
#define DMODEL  1024
#define NHEADS  16
#define DHEAD   64
#define MTOT    (BATCH*SEQ)   // 4096

// Scratch (allocation-free rule: __device__ globals)
__device__ float g_Q[MTOT*DMODEL];
__device__ float g_K[MTOT*DMODEL];
__device__ float g_V[MTOT*DMODEL];
__device__ float g_O[MTOT*DMODEL];

__device__ __forceinline__ float tf32r(float x) {
    asm("cvt.rna.tf32.f32 %0, %0;" : "+f"(x));
    return x;
}

__device__ __forceinline__ void mma_tf32(float c[4], const unsigned a[4], const unsigned b[2]) {
    asm volatile(
        "mma.sync.aligned.m16n8k8.row.col.f32.tf32.tf32.f32 "
        "{%0,%1,%2,%3}, {%4,%5,%6,%7}, {%8,%9}, {%0,%1,%2,%3};\n"
        : "+f"(c[0]), "+f"(c[1]), "+f"(c[2]), "+f"(c[3])
        : "r"(a[0]), "r"(a[1]), "r"(a[2]), "r"(a[3]), "r"(b[0]), "r"(b[1]));
}

// ---------------------------------------------------------------------------
// TF32 tensor-core GEMM: C[M,N] = A[M,K] * B[K,N], row-major.
// 128x128x32 CTA tile, 8 warps, warp tile 64x32 (4x4 grid of m16n8k8 MMAs).
// Smem: As row-major stride 36 (frag-read bank = 4r+k, conflict-free),
//       Bs k-major stride 136 (frag-read bank = 8k+n, conflict-free).
// ---------------------------------------------------------------------------
__global__ __launch_bounds__(256, 2)
void gemm_tf32(const float* __restrict__ A, const float* __restrict__ B,
               float* __restrict__ C, int M, int N, int K)
{
    __shared__ float As[128][36];   // [m][k], stride 36 (144B, 16B-aligned)
    __shared__ float Bs[32][136];   // [k][n], stride 136 (544B, 16B-aligned)

    const int tid  = threadIdx.x;
    const int lane = tid & 31;
    const int warp = tid >> 5;
    const int wm   = warp >> 2;           // 0..1
    const int wn   = warp & 3;            // 0..3
    const int rowW = wm * 64;
    const int colW = wn * 32;
    const int qr   = lane >> 2;           // 0..7
    const int qc   = lane & 3;            // 0..3

    const int rowBase = blockIdx.y * 128;
    const int colBase = blockIdx.x * 128;

    float acc[4][4][4];
    #pragma unroll
    for (int mt = 0; mt < 4; mt++)
        #pragma unroll
        for (int nt = 0; nt < 4; nt++)
            #pragma unroll
            for (int i = 0; i < 4; i++) acc[mt][nt][i] = 0.f;

    for (int k0 = 0; k0 < K; k0 += 32) {
        // Stage A tile 128x32 (tf32-rounded), coalesced float4 loads
        #pragma unroll
        for (int l = 0; l < 4; l++) {
            int idx = tid + l * 256;
            int r = idx >> 3;
            int c = (idx & 7) << 2;
            float4 v = *(const float4*)(A + (size_t)(rowBase + r) * K + k0 + c);
            v.x = tf32r(v.x); v.y = tf32r(v.y); v.z = tf32r(v.z); v.w = tf32r(v.w);
            *(float4*)(&As[r][c]) = v;
        }
        // Stage B tile 32x128
        #pragma unroll
        for (int l = 0; l < 4; l++) {
            int idx = tid + l * 256;
            int r = idx >> 5;
            int c = (idx & 31) << 2;
            float4 v = *(const float4*)(B + (size_t)(k0 + r) * N + colBase + c);
            v.x = tf32r(v.x); v.y = tf32r(v.y); v.z = tf32r(v.z); v.w = tf32r(v.w);
            *(float4*)(&Bs[r][c]) = v;
        }
        __syncthreads();

        #pragma unroll
        for (int kk = 0; kk < 4; kk++) {
            const int k = kk * 8;
            unsigned a[4][4], b[4][2];
            #pragma unroll
            for (int mt = 0; mt < 4; mt++) {
                int rm = rowW + mt * 16 + qr;
                a[mt][0] = __float_as_uint(As[rm    ][k     + qc]);
                a[mt][1] = __float_as_uint(As[rm + 8][k     + qc]);
                a[mt][2] = __float_as_uint(As[rm    ][k + 4 + qc]);
                a[mt][3] = __float_as_uint(As[rm + 8][k + 4 + qc]);
            }
            #pragma unroll
            for (int nt = 0; nt < 4; nt++) {
                int cn = colW + nt * 8 + qr;
                b[nt][0] = __float_as_uint(Bs[k     + qc][cn]);
                b[nt][1] = __float_as_uint(Bs[k + 4 + qc][cn]);
            }
            #pragma unroll
            for (int mt = 0; mt < 4; mt++)
                #pragma unroll
                for (int nt = 0; nt < 4; nt++)
                    mma_tf32(acc[mt][nt], a[mt], b[nt]);
        }
        __syncthreads();
    }

    // Epilogue: c0,c1 at (row, 2qc), c2,c3 at (row+8, 2qc)
    #pragma unroll
    for (int mt = 0; mt < 4; mt++) {
        int r = rowBase + rowW + mt * 16 + qr;
        #pragma unroll
        for (int nt = 0; nt < 4; nt++) {
            int c = colBase + colW + nt * 8 + 2 * qc;
            *(float2*)(C + (size_t)r * N + c)       = make_float2(acc[mt][nt][0], acc[mt][nt][1]);
            *(float2*)(C + (size_t)(r + 8) * N + c) = make_float2(acc[mt][nt][2], acc[mt][nt][3]);
        }
    }
}

// ---------------------------------------------------------------------------
// RoPE applied in-place to Q and K.
// ---------------------------------------------------------------------------
__global__ void rope_kernel(float* __restrict__ Q, float* __restrict__ K,
                            const float* __restrict__ cosT,
                            const float* __restrict__ sinT)
{
    int idx = blockIdx.x * blockDim.x + threadIdx.x;   // [0, MTOT*NHEADS*32)
    int d  = idx & 31;
    int h  = (idx >> 5) & (NHEADS - 1);
    int ms = idx >> 9;                 // b*SEQ + s
    int s  = ms & (SEQ - 1);

    float c  = cosT[s * 32 + d];
    float sn = sinT[s * 32 + d];
    size_t base = (size_t)ms * DMODEL + h * DHEAD + d;

    float x1 = Q[base], x2 = Q[base + 32];
    Q[base]      = x1 * c - x2 * sn;
    Q[base + 32] = x2 * c + x1 * sn;

    float y1 = K[base], y2 = K[base + 32];
    K[base]      = y1 * c - y2 * sn;
    K[base + 32] = y2 * c + y1 * sn;
}

// ---------------------------------------------------------------------------
// Flash attention (fp32, causal) — unchanged from R1.
// ---------------------------------------------------------------------------
__global__ __launch_bounds__(256)
void attn_kernel(const float* __restrict__ Q, const float* __restrict__ K,
                 const float* __restrict__ V, float* __restrict__ O)
{
    extern __shared__ float sm[];
    float* Qs   = sm;                  // 64*64
    float* KSs  = Qs  + 64 * 64;       // 64*65
    float* Vs   = KSs + 64 * 65;       // 64*65
    float* mrow = Vs  + 64 * 65;       // 64
    float* lrow = mrow + 64;           // 64
    float* arow = lrow + 64;           // 64

    const int qb = blockIdx.x, h = blockIdx.y, b = blockIdx.z;
    const int tid = threadIdx.x;
    const int tx = tid & 15, ty = tid >> 4;
    const int r0 = ty * 4, c0 = tx * 4;

    #pragma unroll
    for (int l = 0; l < 4; l++) {
        int f = tid + l * 256;
        int r = f >> 4, c = (f & 15) << 2;
        float4 v4 = *(const float4*)(Q + ((size_t)(b * SEQ + qb * 64 + r)) * DMODEL
                                       + h * DHEAD + c);
        Qs[r * 64 + c + 0] = v4.x; Qs[r * 64 + c + 1] = v4.y;
        Qs[r * 64 + c + 2] = v4.z; Qs[r * 64 + c + 3] = v4.w;
    }
    if (tid < 64) { mrow[tid] = -INFINITY; lrow[tid] = 0.f; }

    float acc[4][4];
    #pragma unroll
    for (int i = 0; i < 4; i++)
        #pragma unroll
        for (int j = 0; j < 4; j++) acc[i][j] = 0.f;
    __syncthreads();

    for (int kj = 0; kj <= qb; kj++) {
        #pragma unroll
        for (int l = 0; l < 4; l++) {
            int f = tid + l * 256;
            int r = f >> 4, c = (f & 15) << 2;
            size_t gb = ((size_t)(b * SEQ + kj * 64 + r)) * DMODEL + h * DHEAD + c;
            float4 kv = *(const float4*)(K + gb);
            KSs[r * 65 + c + 0] = kv.x; KSs[r * 65 + c + 1] = kv.y;
            KSs[r * 65 + c + 2] = kv.z; KSs[r * 65 + c + 3] = kv.w;
            float4 vv = *(const float4*)(V + gb);
            Vs[r * 65 + c + 0] = vv.x; Vs[r * 65 + c + 1] = vv.y;
            Vs[r * 65 + c + 2] = vv.z; Vs[r * 65 + c + 3] = vv.w;
        }
        __syncthreads();

        float sreg[4][4];
        #pragma unroll
        for (int i = 0; i < 4; i++)
            #pragma unroll
            for (int j = 0; j < 4; j++) sreg[i][j] = 0.f;

        #pragma unroll 4
        for (int d = 0; d < 64; d++) {
            float rq[4], rk[4];
            #pragma unroll
            for (int i = 0; i < 4; i++) rq[i] = Qs[(r0 + i) * 64 + d];
            #pragma unroll
            for (int j = 0; j < 4; j++) rk[j] = KSs[(c0 + j) * 65 + d];
            #pragma unroll
            for (int i = 0; i < 4; i++)
                #pragma unroll
                for (int j = 0; j < 4; j++)
                    sreg[i][j] = fmaf(rq[i], rk[j], sreg[i][j]);
        }
        __syncthreads();

        const int qrow = qb * 64, kcol = kj * 64;
        #pragma unroll
        for (int i = 0; i < 4; i++)
            #pragma unroll
            for (int j = 0; j < 4; j++) {
                float sv = sreg[i][j] * 0.125f;
                if (kcol + c0 + j > qrow + r0 + i) sv = -1e30f;
                KSs[(r0 + i) * 65 + c0 + j] = sv;
            }
        __syncthreads();

        if (tid < 64) {
            int r = tid;
            float mold = mrow[r], mx = mold;
            #pragma unroll 8
            for (int j = 0; j < 64; j++) mx = fmaxf(mx, KSs[r * 65 + j]);
            float a = __expf(mold - mx);
            float sum = 0.f;
            #pragma unroll 8
            for (int j = 0; j < 64; j++) {
                float p = __expf(KSs[r * 65 + j] - mx);
                KSs[r * 65 + j] = p;
                sum += p;
            }
            mrow[r] = mx;
            lrow[r] = lrow[r] * a + sum;
            arow[r] = a;
        }
        __syncthreads();

        float al[4];
        #pragma unroll
        for (int i = 0; i < 4; i++) al[i] = arow[r0 + i];
        #pragma unroll
        for (int i = 0; i < 4; i++)
            #pragma unroll
            for (int j = 0; j < 4; j++) acc[i][j] *= al[i];

        #pragma unroll 4
        for (int kk = 0; kk < 64; kk++) {
            float rp[4], rv[4];
            #pragma unroll
            for (int i = 0; i < 4; i++) rp[i] = KSs[(r0 + i) * 65 + kk];
            #pragma unroll
            for (int j = 0; j < 4; j++) rv[j] = Vs[kk * 65 + c0 + j];
            #pragma unroll
            for (int i = 0; i < 4; i++)
                #pragma unroll
                for (int j = 0; j < 4; j++)
                    acc[i][j] = fmaf(rp[i], rv[j], acc[i][j]);
        }
        __syncthreads();
    }

    #pragma unroll
    for (int i = 0; i < 4; i++) {
        float inv = 1.0f / lrow[r0 + i];
        size_t base = ((size_t)(b * SEQ + qb * 64 + r0 + i)) * DMODEL + h * DHEAD;
        float4 o4 = make_float4(acc[i][0] * inv, acc[i][1] * inv,
                                acc[i][2] * inv, acc[i][3] * inv);
        *(float4*)(O + base + c0) = o4;
    }
}

// ---------------------------------------------------------------------------
// Launch
// ---------------------------------------------------------------------------
extern "C" void kernel_launch(void* const* d_in, const int* in_sizes, int n_in,
                              void* d_out, int out_size)
{
    const float* hidden = (const float*)d_in[0];
    const float* cosT   = (const float*)d_in[1];
    const float* sinT   = (const float*)d_in[2];
    // d_in[3] = attention_mask (pure causal; reproduced analytically)
    const float* Wq     = (const float*)d_in[4];
    const float* Wk     = (const float*)d_in[5];
    const float* Wv     = (const float*)d_in[6];
    const float* Wo     = (const float*)d_in[7];
    float* out = (float*)d_out;

    float *Qp, *Kp, *Vp, *Op;
    cudaGetSymbolAddress((void**)&Qp, g_Q);
    cudaGetSymbolAddress((void**)&Kp, g_K);
    cudaGetSymbolAddress((void**)&Vp, g_V);
    cudaGetSymbolAddress((void**)&Op, g_O);

    const int attn_smem = (64 * 64 + 2 * 64 * 65 + 3 * 64) * (int)sizeof(float); // 50432
    cudaFuncSetAttribute(attn_kernel, cudaFuncAttributeMaxDynamicSharedMemorySize,
                         attn_smem);

    dim3 gg(DMODEL / 128, MTOT / 128);   // (8, 32)

    gemm_tf32<<<gg, 256>>>(hidden, Wq, Qp, MTOT, DMODEL, DMODEL);
    gemm_tf32<<<gg, 256>>>(hidden, Wk, Kp, MTOT, DMODEL, DMODEL);
    gemm_tf32<<<gg, 256>>>(hidden, Wv, Vp, MTOT, DMODEL, DMODEL);

    rope_kernel<<<(MTOT * NHEADS * 32) / 256, 256>>>(Qp, Kp, cosT, sinT);

    attn_kernel<<<dim3(SEQ / 64, NHEADS, BATCH), 256, attn_smem>>>(Qp, Kp, Vp, Op);

    gemm_tf32<<<gg, 256>>>(Op, Wo, out, MTOT, DMODEL, DMODEL);
}

// round 4
// speedup vs baseline: 1.9753x; 1.3182x over previous
#include <cuda_runtime.h>
#include <math.h>
#include <stdint.h>

#define BATCH   2
#define SEQ     2048
#define DMODEL  1024
#define NHEADS  16
#define DHEAD   64
#define MTOT    (BATCH*SEQ)   // 4096

// Scratch (allocation-free rule: __device__ globals)
__device__ float g_Q[MTOT*DMODEL];
__device__ float g_K[MTOT*DMODEL];
__device__ float g_V[MTOT*DMODEL];
__device__ float g_O[MTOT*DMODEL];

__device__ __forceinline__ float tf32r(float x) {
    asm("cvt.rna.tf32.f32 %0, %0;" : "+f"(x));
    return x;
}
__device__ __forceinline__ unsigned u32(float x) { return __float_as_uint(x); }

// split v into tf32 hi + tf32 lo (residual), hi+lo ~ v to ~2^-22
__device__ __forceinline__ float2 split2f(float v) {
    float h = tf32r(v);
    return make_float2(h, tf32r(v - h));
}

__device__ __forceinline__ void mma_tf32(float c[4], const unsigned a[4], const unsigned b[2]) {
    asm volatile(
        "mma.sync.aligned.m16n8k8.row.col.f32.tf32.tf32.f32 "
        "{%0,%1,%2,%3}, {%4,%5,%6,%7}, {%8,%9}, {%0,%1,%2,%3};\n"
        : "+f"(c[0]), "+f"(c[1]), "+f"(c[2]), "+f"(c[3])
        : "r"(a[0]), "r"(a[1]), "r"(a[2]), "r"(a[3]), "r"(b[0]), "r"(b[1]));
}

__device__ __forceinline__ void cp_async16(uint32_t dst, const void* src) {
    asm volatile("cp.async.cg.shared.global [%0], [%1], 16;" :: "r"(dst), "l"(src));
}

// ---------------------------------------------------------------------------
// TF32 GEMM, cp.async double-buffered. C[M,N] = A[M,K]*B[K,N] row-major.
// 128x128x32 tile, 8 warps (warp tile 64x32). Raw fp32 staged; tf32 cvt at
// fragment read. Dynamic smem: 2 x (128*36 + 32*136) floats = 71680 B.
// ---------------------------------------------------------------------------
#define GEMM_SMEM (2 * (128*36 + 32*136) * 4)

__global__ __launch_bounds__(256, 2)
void gemm_tf32(const float* __restrict__ A, const float* __restrict__ B,
               float* __restrict__ C, int M, int N, int K)
{
    extern __shared__ float gsm[];

    const int tid  = threadIdx.x;
    const int lane = tid & 31;
    const int warp = tid >> 5;
    const int wm   = warp >> 2;
    const int wn   = warp & 3;
    const int rowW = wm * 64;
    const int colW = wn * 32;
    const int qr   = lane >> 2;
    const int qc   = lane & 3;

    const int rowBase = blockIdx.y * 128;
    const int colBase = blockIdx.x * 128;

    const int rA = tid >> 3, cA = (tid & 7) << 2;   // rows rA+32l, cols cA..cA+3
    const int rB = tid >> 5, cB = (tid & 31) << 2;  // rows rB+8l

    const uint32_t sbase = (uint32_t)__cvta_generic_to_shared(gsm);

    auto stage = [&](int buf, int k0) {
        uint32_t abuf = sbase + (uint32_t)buf * 8960u * 4u;
        uint32_t bbuf = abuf + 4608u * 4u;
        #pragma unroll
        for (int l = 0; l < 4; l++) {
            int r  = rA + 32 * l;
            cp_async16(abuf + (uint32_t)(r * 36 + cA) * 4u,
                       A + (size_t)(rowBase + r) * K + k0 + cA);
            int rb = rB + 8 * l;
            cp_async16(bbuf + (uint32_t)(rb * 136 + cB) * 4u,
                       B + (size_t)(k0 + rb) * N + colBase + cB);
        }
        asm volatile("cp.async.commit_group;");
    };

    float acc[4][4][4];
    #pragma unroll
    for (int mt = 0; mt < 4; mt++)
        #pragma unroll
        for (int nt = 0; nt < 4; nt++)
            #pragma unroll
            for (int i = 0; i < 4; i++) acc[mt][nt][i] = 0.f;

    stage(0, 0);
    int buf = 0;
    for (int k0 = 0; k0 < K; k0 += 32) {
        asm volatile("cp.async.wait_group 0;");
        __syncthreads();
        if (k0 + 32 < K) stage(buf ^ 1, k0 + 32);

        const float* As = gsm + buf * 8960;      // [128][36]
        const float* Bs = As + 4608;             // [32][136]

        #pragma unroll
        for (int kk = 0; kk < 4; kk++) {
            const int k = kk * 8;
            unsigned a[4][4], bf[4][2];
            #pragma unroll
            for (int mt = 0; mt < 4; mt++) {
                int r = rowW + mt * 16 + qr;
                a[mt][0] = u32(tf32r(As[r * 36 + k + qc]));
                a[mt][1] = u32(tf32r(As[(r + 8) * 36 + k + qc]));
                a[mt][2] = u32(tf32r(As[r * 36 + k + 4 + qc]));
                a[mt][3] = u32(tf32r(As[(r + 8) * 36 + k + 4 + qc]));
            }
            #pragma unroll
            for (int nt = 0; nt < 4; nt++) {
                int cn = colW + nt * 8 + qr;
                bf[nt][0] = u32(tf32r(Bs[(k + qc) * 136 + cn]));
                bf[nt][1] = u32(tf32r(Bs[(k + 4 + qc) * 136 + cn]));
            }
            #pragma unroll
            for (int mt = 0; mt < 4; mt++)
                #pragma unroll
                for (int nt = 0; nt < 4; nt++)
                    mma_tf32(acc[mt][nt], a[mt], bf[nt]);
        }
        buf ^= 1;
    }

    #pragma unroll
    for (int mt = 0; mt < 4; mt++) {
        int r = rowBase + rowW + mt * 16 + qr;
        #pragma unroll
        for (int nt = 0; nt < 4; nt++) {
            int c = colBase + colW + nt * 8 + 2 * qc;
            *(float2*)(C + (size_t)r * N + c)       = make_float2(acc[mt][nt][0], acc[mt][nt][1]);
            *(float2*)(C + (size_t)(r + 8) * N + c) = make_float2(acc[mt][nt][2], acc[mt][nt][3]);
        }
    }
}

// ---------------------------------------------------------------------------
// RoPE applied in-place to Q and K.
// ---------------------------------------------------------------------------
__global__ void rope_kernel(float* __restrict__ Q, float* __restrict__ K,
                            const float* __restrict__ cosT,
                            const float* __restrict__ sinT)
{
    int idx = blockIdx.x * blockDim.x + threadIdx.x;
    int d  = idx & 31;
    int h  = (idx >> 5) & (NHEADS - 1);
    int ms = idx >> 9;
    int s  = ms & (SEQ - 1);

    float c  = cosT[s * 32 + d];
    float sn = sinT[s * 32 + d];
    size_t base = (size_t)ms * DMODEL + h * DHEAD + d;

    float x1 = Q[base], x2 = Q[base + 32];
    Q[base]      = x1 * c - x2 * sn;
    Q[base + 32] = x2 * c + x1 * sn;

    float y1 = K[base], y2 = K[base + 32];
    K[base]      = y1 * c - y2 * sn;
    K[base + 32] = y2 * c + y1 * sn;
}

// ---------------------------------------------------------------------------
// Flash attention on tensor cores, 3-term tf32 split (near-fp32 accuracy).
// Block: 64 q-rows x (kv tiles of 64), 4 warps; warp owns 16 q-rows.
// Smem (dynamic, 71680 B):
//   KP[64][136]: K tile as (hi,lo) float pairs; after QK^T reused for P(hi,lo)
//   VS[64][144]: V tile as (hi,lo) pairs, [token][dh]
// Q fragments (hi/lo) live in registers for the whole block.
// ---------------------------------------------------------------------------
#define ATTN_SMEM ((64*136 + 64*144) * 4)

__global__ __launch_bounds__(128, 3)
void attn_mma(const float* __restrict__ Q, const float* __restrict__ K,
              const float* __restrict__ V, float* __restrict__ O)
{
    extern __shared__ float smf[];
    float* KP = smf;              // [64][136]
    float* VS = smf + 64 * 136;   // [64][144]

    const int qb = blockIdx.x, h = blockIdx.y, b = blockIdx.z;
    const int tid = threadIdx.x;
    const int lane = tid & 31, w = tid >> 5;
    const int qr = lane >> 2, qc = lane & 3;
    const int rm = w * 16 + qr;

    const size_t headOff = (size_t)h * DHEAD;
    const size_t rowQ0 = (size_t)b * SEQ + (size_t)qb * 64;

    // ---- Q fragments (hi/lo), read directly from gmem, one-time ----
    unsigned qhi[8][4], qlo[8][4];
    {
        const float* qp = Q + rowQ0 * DMODEL + headOff;
        #pragma unroll
        for (int ks = 0; ks < 8; ks++) {
            int k = ks * 8;
            float2 t;
            t = split2f(qp[(size_t)rm * DMODEL + k + qc]);           qhi[ks][0] = u32(t.x); qlo[ks][0] = u32(t.y);
            t = split2f(qp[(size_t)(rm + 8) * DMODEL + k + qc]);     qhi[ks][1] = u32(t.x); qlo[ks][1] = u32(t.y);
            t = split2f(qp[(size_t)rm * DMODEL + k + 4 + qc]);       qhi[ks][2] = u32(t.x); qlo[ks][2] = u32(t.y);
            t = split2f(qp[(size_t)(rm + 8) * DMODEL + k + 4 + qc]); qhi[ks][3] = u32(t.x); qlo[ks][3] = u32(t.y);
        }
    }

    float o[8][4];
    #pragma unroll
    for (int nt = 0; nt < 8; nt++)
        #pragma unroll
        for (int i = 0; i < 4; i++) o[nt][i] = 0.f;
    float m0 = -3.0e38f, m1 = -3.0e38f, l0 = 0.f, l1 = 0.f;

    const int rowg0 = qb * 64 + rm;
    const int rowg1 = rowg0 + 8;

    for (int kj = 0; kj <= qb; kj++) {
        // ---- stage K/V tiles as (hi,lo) pairs ----
        const float* kp = K + ((size_t)b * SEQ + (size_t)kj * 64) * DMODEL + headOff;
        const float* vp = V + ((size_t)b * SEQ + (size_t)kj * 64) * DMODEL + headOff;
        #pragma unroll
        for (int l = 0; l < 8; l++) {
            int idx = tid + l * 128;
            int r = idx >> 4, c = (idx & 15) << 2;
            float4 kv = *(const float4*)(kp + (size_t)r * DMODEL + c);
            float2 s0 = split2f(kv.x), s1 = split2f(kv.y), s2 = split2f(kv.z), s3 = split2f(kv.w);
            float* dk = KP + r * 136 + 2 * c;
            *(float4*)(dk)     = make_float4(s0.x, s0.y, s1.x, s1.y);
            *(float4*)(dk + 4) = make_float4(s2.x, s2.y, s3.x, s3.y);
            float4 vv = *(const float4*)(vp + (size_t)r * DMODEL + c);
            s0 = split2f(vv.x); s1 = split2f(vv.y); s2 = split2f(vv.z); s3 = split2f(vv.w);
            float* dv = VS + r * 144 + 2 * c;
            *(float4*)(dv)     = make_float4(s0.x, s0.y, s1.x, s1.y);
            *(float4*)(dv + 4) = make_float4(s2.x, s2.y, s3.x, s3.y);
        }
        __syncthreads();

        // ---- S = Q K^T (3-term split) ----
        float s[8][4];
        #pragma unroll
        for (int nt = 0; nt < 8; nt++)
            #pragma unroll
            for (int i = 0; i < 4; i++) s[nt][i] = 0.f;

        #pragma unroll
        for (int ks = 0; ks < 8; ks++) {
            const int k = ks * 8;
            #pragma unroll
            for (int nt = 0; nt < 8; nt++) {
                int cn = nt * 8 + qr;
                float2 b0 = *(const float2*)(KP + cn * 136 + 2 * (k + qc));
                float2 b1 = *(const float2*)(KP + cn * 136 + 2 * (k + 4 + qc));
                unsigned bh[2] = { u32(b0.x), u32(b1.x) };
                unsigned bl[2] = { u32(b0.y), u32(b1.y) };
                mma_tf32(s[nt], qhi[ks], bh);
                mma_tf32(s[nt], qhi[ks], bl);
                mma_tf32(s[nt], qlo[ks], bh);
            }
        }
        __syncthreads();   // K reads done; KP region becomes P

        // ---- scale + causal mask + row max ----
        float mx0 = m0, mx1 = m1;
        #pragma unroll
        for (int nt = 0; nt < 8; nt++) {
            int cg = kj * 64 + nt * 8 + 2 * qc;
            #pragma unroll
            for (int d = 0; d < 2; d++) {
                float v0 = s[nt][d] * 0.125f;
                if (cg + d > rowg0) v0 = -1e30f;
                s[nt][d] = v0; mx0 = fmaxf(mx0, v0);
                float v1 = s[nt][2 + d] * 0.125f;
                if (cg + d > rowg1) v1 = -1e30f;
                s[nt][2 + d] = v1; mx1 = fmaxf(mx1, v1);
            }
        }
        mx0 = fmaxf(mx0, __shfl_xor_sync(0xffffffffu, mx0, 1));
        mx0 = fmaxf(mx0, __shfl_xor_sync(0xffffffffu, mx0, 2));
        mx1 = fmaxf(mx1, __shfl_xor_sync(0xffffffffu, mx1, 1));
        mx1 = fmaxf(mx1, __shfl_xor_sync(0xffffffffu, mx1, 2));

        float a0 = __expf(m0 - mx0);
        float a1 = __expf(m1 - mx1);
        m0 = mx0; m1 = mx1;

        float rs0 = 0.f, rs1 = 0.f;
        #pragma unroll
        for (int nt = 0; nt < 8; nt++) {
            float p0 = __expf(s[nt][0] - mx0), p1 = __expf(s[nt][1] - mx0);
            float p2 = __expf(s[nt][2] - mx1), p3 = __expf(s[nt][3] - mx1);
            rs0 += p0 + p1; rs1 += p2 + p3;
            float2 h0 = split2f(p0), h1 = split2f(p1), h2 = split2f(p2), h3 = split2f(p3);
            float* d0 = KP + rm * 136 + 2 * (nt * 8 + 2 * qc);
            *(float4*)(d0) = make_float4(h0.x, h0.y, h1.x, h1.y);
            float* d1 = KP + (rm + 8) * 136 + 2 * (nt * 8 + 2 * qc);
            *(float4*)(d1) = make_float4(h2.x, h2.y, h3.x, h3.y);
        }
        rs0 += __shfl_xor_sync(0xffffffffu, rs0, 1);
        rs0 += __shfl_xor_sync(0xffffffffu, rs0, 2);
        rs1 += __shfl_xor_sync(0xffffffffu, rs1, 1);
        rs1 += __shfl_xor_sync(0xffffffffu, rs1, 2);
        l0 = l0 * a0 + rs0;
        l1 = l1 * a1 + rs1;

        #pragma unroll
        for (int nt = 0; nt < 8; nt++) {
            o[nt][0] *= a0; o[nt][1] *= a0;
            o[nt][2] *= a1; o[nt][3] *= a1;
        }
        __syncthreads();   // P visible to all warps

        // ---- O += P V (3-term split) ----
        #pragma unroll
        for (int ks = 0; ks < 8; ks++) {
            const int k = ks * 8;
            unsigned ah[4], al[4];
            float2 t;
            t = *(const float2*)(KP + rm * 136 + 2 * (k + qc));           ah[0] = u32(t.x); al[0] = u32(t.y);
            t = *(const float2*)(KP + (rm + 8) * 136 + 2 * (k + qc));     ah[1] = u32(t.x); al[1] = u32(t.y);
            t = *(const float2*)(KP + rm * 136 + 2 * (k + 4 + qc));       ah[2] = u32(t.x); al[2] = u32(t.y);
            t = *(const float2*)(KP + (rm + 8) * 136 + 2 * (k + 4 + qc)); ah[3] = u32(t.x); al[3] = u32(t.y);
            #pragma unroll
            for (int nt = 0; nt < 8; nt++) {
                float2 b0 = *(const float2*)(VS + (k + qc) * 144 + 2 * (nt * 8 + qr));
                float2 b1 = *(const float2*)(VS + (k + 4 + qc) * 144 + 2 * (nt * 8 + qr));
                unsigned bh[2] = { u32(b0.x), u32(b1.x) };
                unsigned bl[2] = { u32(b0.y), u32(b1.y) };
                mma_tf32(o[nt], ah, bh);
                mma_tf32(o[nt], ah, bl);
                mma_tf32(o[nt], al, bh);
            }
        }
        __syncthreads();   // reads done before next tile staging
    }

    // ---- normalize + write ----
    float inv0 = 1.0f / l0, inv1 = 1.0f / l1;
    float* op = O + rowQ0 * DMODEL + headOff;
    #pragma unroll
    for (int nt = 0; nt < 8; nt++) {
        int c = nt * 8 + 2 * qc;
        *(float2*)(op + (size_t)rm * DMODEL + c)       = make_float2(o[nt][0] * inv0, o[nt][1] * inv0);
        *(float2*)(op + (size_t)(rm + 8) * DMODEL + c) = make_float2(o[nt][2] * inv1, o[nt][3] * inv1);
    }
}

// ---------------------------------------------------------------------------
// Launch
// ---------------------------------------------------------------------------
extern "C" void kernel_launch(void* const* d_in, const int* in_sizes, int n_in,
                              void* d_out, int out_size)
{
    const float* hidden = (const float*)d_in[0];
    const float* cosT   = (const float*)d_in[1];
    const float* sinT   = (const float*)d_in[2];
    // d_in[3] = attention_mask (pure causal; reproduced analytically)
    const float* Wq     = (const float*)d_in[4];
    const float* Wk     = (const float*)d_in[5];
    const float* Wv     = (const float*)d_in[6];
    const float* Wo     = (const float*)d_in[7];
    float* out = (float*)d_out;

    float *Qp, *Kp, *Vp, *Op;
    cudaGetSymbolAddress((void**)&Qp, g_Q);
    cudaGetSymbolAddress((void**)&Kp, g_K);
    cudaGetSymbolAddress((void**)&Vp, g_V);
    cudaGetSymbolAddress((void**)&Op, g_O);

    cudaFuncSetAttribute(gemm_tf32, cudaFuncAttributeMaxDynamicSharedMemorySize, GEMM_SMEM);
    cudaFuncSetAttribute(attn_mma,  cudaFuncAttributeMaxDynamicSharedMemorySize, ATTN_SMEM);

    dim3 gg(DMODEL / 128, MTOT / 128);   // (8, 32)

    gemm_tf32<<<gg, 256, GEMM_SMEM>>>(hidden, Wq, Qp, MTOT, DMODEL, DMODEL);
    gemm_tf32<<<gg, 256, GEMM_SMEM>>>(hidden, Wk, Kp, MTOT, DMODEL, DMODEL);
    gemm_tf32<<<gg, 256, GEMM_SMEM>>>(hidden, Wv, Vp, MTOT, DMODEL, DMODEL);

    rope_kernel<<<(MTOT * NHEADS * 32) / 256, 256>>>(Qp, Kp, cosT, sinT);

    attn_mma<<<dim3(SEQ / 64, NHEADS, BATCH), 128, ATTN_SMEM>>>(Qp, Kp, Vp, Op);

    gemm_tf32<<<gg, 256, GEMM_SMEM>>>(Op, Wo, out, MTOT, DMODEL, DMODEL);
}

// round 5
// speedup vs baseline: 3.1029x; 1.5709x over previous
#include <cuda_runtime.h>
#include <cuda_bf16.h>
#include <math.h>
#include <stdint.h>

#define BATCH   2
#define SEQ     2048
#define DMODEL  1024
#define NHEADS  16
#define DHEAD   64
#define MTOT    (BATCH*SEQ)   // 4096

// Scratch (allocation-free rule: __device__ globals)
__device__ float g_Q[MTOT*DMODEL];
__device__ float g_K[MTOT*DMODEL];
__device__ float g_V[MTOT*DMODEL];
__device__ float g_O[MTOT*DMODEL];

__device__ __forceinline__ float tf32r(float x) {
    asm("cvt.rna.tf32.f32 %0, %0;" : "+f"(x));
    return x;
}
__device__ __forceinline__ unsigned u32(float x) { return __float_as_uint(x); }

__device__ __forceinline__ void mma_tf32(float c[4], const unsigned a[4], const unsigned b[2]) {
    asm volatile(
        "mma.sync.aligned.m16n8k8.row.col.f32.tf32.tf32.f32 "
        "{%0,%1,%2,%3}, {%4,%5,%6,%7}, {%8,%9}, {%0,%1,%2,%3};\n"
        : "+f"(c[0]), "+f"(c[1]), "+f"(c[2]), "+f"(c[3])
        : "r"(a[0]), "r"(a[1]), "r"(a[2]), "r"(a[3]), "r"(b[0]), "r"(b[1]));
}

__device__ __forceinline__ void mma_bf16(float c[4], const unsigned a[4], const unsigned b[2]) {
    asm volatile(
        "mma.sync.aligned.m16n8k16.row.col.f32.bf16.bf16.f32 "
        "{%0,%1,%2,%3}, {%4,%5,%6,%7}, {%8,%9}, {%0,%1,%2,%3};\n"
        : "+f"(c[0]), "+f"(c[1]), "+f"(c[2]), "+f"(c[3])
        : "r"(a[0]), "r"(a[1]), "r"(a[2]), "r"(a[3]), "r"(b[0]), "r"(b[1]));
}

__device__ __forceinline__ void ldmx2t(unsigned &d0, unsigned &d1, uint32_t addr) {
    asm volatile("ldmatrix.sync.aligned.m8n8.x2.trans.shared.b16 {%0,%1}, [%2];"
                 : "=r"(d0), "=r"(d1) : "r"(addr));
}

__device__ __forceinline__ unsigned bfpack(float a, float b) {
    __nv_bfloat162 h = __floats2bfloat162_rn(a, b);   // .x = a (low half, lower k)
    return *reinterpret_cast<unsigned*>(&h);
}
// split pair (a,b) into bf16 hi-plane u32 and bf16 lo-plane (residual) u32
__device__ __forceinline__ void bfsplit2(float a, float b, unsigned &hi, unsigned &lo) {
    float ha = __bfloat162float(__float2bfloat16_rn(a));
    float hb = __bfloat162float(__float2bfloat16_rn(b));
    hi = bfpack(ha, hb);
    lo = bfpack(a - ha, b - hb);
}

__device__ __forceinline__ void cp_async16(uint32_t dst, const void* src) {
    asm volatile("cp.async.cg.shared.global [%0], [%1], 16;" :: "r"(dst), "l"(src));
}

// ---------------------------------------------------------------------------
// TF32 GEMM, cp.async double-buffered (unchanged from R4).
// ---------------------------------------------------------------------------
#define GEMM_SMEM (2 * (128*36 + 32*136) * 4)

__global__ __launch_bounds__(256, 2)
void gemm_tf32(const float* __restrict__ A, const float* __restrict__ B,
               float* __restrict__ C, int M, int N, int K)
{
    extern __shared__ float gsm[];

    const int tid  = threadIdx.x;
    const int lane = tid & 31;
    const int warp = tid >> 5;
    const int wm   = warp >> 2;
    const int wn   = warp & 3;
    const int rowW = wm * 64;
    const int colW = wn * 32;
    const int qr   = lane >> 2;
    const int qc   = lane & 3;

    const int rowBase = blockIdx.y * 128;
    const int colBase = blockIdx.x * 128;

    const int rA = tid >> 3, cA = (tid & 7) << 2;
    const int rB = tid >> 5, cB = (tid & 31) << 2;

    const uint32_t sbase = (uint32_t)__cvta_generic_to_shared(gsm);

    auto stage = [&](int buf, int k0) {
        uint32_t abuf = sbase + (uint32_t)buf * 8960u * 4u;
        uint32_t bbuf = abuf + 4608u * 4u;
        #pragma unroll
        for (int l = 0; l < 4; l++) {
            int r  = rA + 32 * l;
            cp_async16(abuf + (uint32_t)(r * 36 + cA) * 4u,
                       A + (size_t)(rowBase + r) * K + k0 + cA);
            int rb = rB + 8 * l;
            cp_async16(bbuf + (uint32_t)(rb * 136 + cB) * 4u,
                       B + (size_t)(k0 + rb) * N + colBase + cB);
        }
        asm volatile("cp.async.commit_group;");
    };

    float acc[4][4][4];
    #pragma unroll
    for (int mt = 0; mt < 4; mt++)
        #pragma unroll
        for (int nt = 0; nt < 4; nt++)
            #pragma unroll
            for (int i = 0; i < 4; i++) acc[mt][nt][i] = 0.f;

    stage(0, 0);
    int buf = 0;
    for (int k0 = 0; k0 < K; k0 += 32) {
        asm volatile("cp.async.wait_group 0;");
        __syncthreads();
        if (k0 + 32 < K) stage(buf ^ 1, k0 + 32);

        const float* As = gsm + buf * 8960;
        const float* Bs = As + 4608;

        #pragma unroll
        for (int kk = 0; kk < 4; kk++) {
            const int k = kk * 8;
            unsigned a[4][4], bf[4][2];
            #pragma unroll
            for (int mt = 0; mt < 4; mt++) {
                int r = rowW + mt * 16 + qr;
                a[mt][0] = u32(tf32r(As[r * 36 + k + qc]));
                a[mt][1] = u32(tf32r(As[(r + 8) * 36 + k + qc]));
                a[mt][2] = u32(tf32r(As[r * 36 + k + 4 + qc]));
                a[mt][3] = u32(tf32r(As[(r + 8) * 36 + k + 4 + qc]));
            }
            #pragma unroll
            for (int nt = 0; nt < 4; nt++) {
                int cn = colW + nt * 8 + qr;
                bf[nt][0] = u32(tf32r(Bs[(k + qc) * 136 + cn]));
                bf[nt][1] = u32(tf32r(Bs[(k + 4 + qc) * 136 + cn]));
            }
            #pragma unroll
            for (int mt = 0; mt < 4; mt++)
                #pragma unroll
                for (int nt = 0; nt < 4; nt++)
                    mma_tf32(acc[mt][nt], a[mt], bf[nt]);
        }
        buf ^= 1;
    }

    #pragma unroll
    for (int mt = 0; mt < 4; mt++) {
        int r = rowBase + rowW + mt * 16 + qr;
        #pragma unroll
        for (int nt = 0; nt < 4; nt++) {
            int c = colBase + colW + nt * 8 + 2 * qc;
            *(float2*)(C + (size_t)r * N + c)       = make_float2(acc[mt][nt][0], acc[mt][nt][1]);
            *(float2*)(C + (size_t)(r + 8) * N + c) = make_float2(acc[mt][nt][2], acc[mt][nt][3]);
        }
    }
}

// ---------------------------------------------------------------------------
// RoPE (unchanged).
// ---------------------------------------------------------------------------
__global__ void rope_kernel(float* __restrict__ Q, float* __restrict__ K,
                            const float* __restrict__ cosT,
                            const float* __restrict__ sinT)
{
    int idx = blockIdx.x * blockDim.x + threadIdx.x;
    int d  = idx & 31;
    int h  = (idx >> 5) & (NHEADS - 1);
    int ms = idx >> 9;
    int s  = ms & (SEQ - 1);

    float c  = cosT[s * 32 + d];
    float sn = sinT[s * 32 + d];
    size_t base = (size_t)ms * DMODEL + h * DHEAD + d;

    float x1 = Q[base], x2 = Q[base + 32];
    Q[base]      = x1 * c - x2 * sn;
    Q[base + 32] = x2 * c + x1 * sn;

    float y1 = K[base], y2 = K[base + 32];
    K[base]      = y1 * c - y2 * sn;
    K[base + 32] = y2 * c + y1 * sn;
}

// ---------------------------------------------------------------------------
// Flash attention: bf16 3-term split (hi/lo planes), m16n8k16 MMAs.
// 64 q-rows/block, 4 warps (16 q-rows each), 64-token kv tiles.
// Smem planes (bf16, stride 72): KH/KL [64][72] (aliased by PH/PL after QK^T),
// VH/VL [64][72] natural [token][dh]; PV B-frags via ldmatrix.x2.trans.
// Total smem = 4*4608*2 = 36864 B.
// ---------------------------------------------------------------------------
#define ATTN_SMEM (4 * 4608 * 2)

__global__ __launch_bounds__(128, 4)
void attn_mma(const float* __restrict__ Q, const float* __restrict__ K,
              const float* __restrict__ V, float* __restrict__ O)
{
    extern __shared__ __nv_bfloat16 smb[];
    __nv_bfloat16* KH = smb;               // [64][72]   (later PH)
    __nv_bfloat16* KL = smb + 4608;        // [64][72]   (later PL)
    __nv_bfloat16* VH = smb + 2 * 4608;    // [64][72]
    __nv_bfloat16* VL = smb + 3 * 4608;    // [64][72]

    const uint32_t vhb = (uint32_t)__cvta_generic_to_shared(VH);
    const uint32_t vlb = (uint32_t)__cvta_generic_to_shared(VL);

    const int qb = blockIdx.x, h = blockIdx.y, b = blockIdx.z;
    const int tid = threadIdx.x;
    const int lane = tid & 31, w = tid >> 5;
    const int qr = lane >> 2, qc = lane & 3;
    const int rm = w * 16 + qr;
    const int l15 = lane & 15;             // ldmatrix row select

    const size_t headOff = (size_t)h * DHEAD;
    const size_t rowQ0 = (size_t)b * SEQ + (size_t)qb * 64;

    // ---- Q fragments (bf16 hi/lo), one-time from gmem ----
    unsigned qhi[4][4], qlo[4][4];
    {
        const float* qp = Q + rowQ0 * DMODEL + headOff;
        #pragma unroll
        for (int ks = 0; ks < 4; ks++) {
            int k = ks * 16;
            float2 t;
            t = *(const float2*)(qp + (size_t)rm * DMODEL + k + 2 * qc);
            bfsplit2(t.x, t.y, qhi[ks][0], qlo[ks][0]);
            t = *(const float2*)(qp + (size_t)(rm + 8) * DMODEL + k + 2 * qc);
            bfsplit2(t.x, t.y, qhi[ks][1], qlo[ks][1]);
            t = *(const float2*)(qp + (size_t)rm * DMODEL + k + 8 + 2 * qc);
            bfsplit2(t.x, t.y, qhi[ks][2], qlo[ks][2]);
            t = *(const float2*)(qp + (size_t)(rm + 8) * DMODEL + k + 8 + 2 * qc);
            bfsplit2(t.x, t.y, qhi[ks][3], qlo[ks][3]);
        }
    }

    float o[8][4];
    #pragma unroll
    for (int nt = 0; nt < 8; nt++)
        #pragma unroll
        for (int i = 0; i < 4; i++) o[nt][i] = 0.f;
    float m0 = -3.0e38f, m1 = -3.0e38f, l0 = 0.f, l1 = 0.f;

    const int rowg0 = qb * 64 + rm;
    const int rowg1 = rowg0 + 8;

    for (int kj = 0; kj <= qb; kj++) {
        // ---- stage K,V tiles as bf16 hi/lo planes ----
        const float* kp = K + ((size_t)b * SEQ + (size_t)kj * 64) * DMODEL + headOff;
        const float* vp = V + ((size_t)b * SEQ + (size_t)kj * 64) * DMODEL + headOff;
        #pragma unroll
        for (int l = 0; l < 8; l++) {
            int idx = tid + l * 128;
            int r = idx >> 4, c = (idx & 15) << 2;
            float4 kv = *(const float4*)(kp + (size_t)r * DMODEL + c);
            unsigned hA, lA, hB, lB;
            bfsplit2(kv.x, kv.y, hA, lA);
            bfsplit2(kv.z, kv.w, hB, lB);
            *(unsigned*)(KH + r * 72 + c)     = hA;
            *(unsigned*)(KH + r * 72 + c + 2) = hB;
            *(unsigned*)(KL + r * 72 + c)     = lA;
            *(unsigned*)(KL + r * 72 + c + 2) = lB;
            float4 vv = *(const float4*)(vp + (size_t)r * DMODEL + c);
            bfsplit2(vv.x, vv.y, hA, lA);
            bfsplit2(vv.z, vv.w, hB, lB);
            *(unsigned*)(VH + r * 72 + c)     = hA;
            *(unsigned*)(VH + r * 72 + c + 2) = hB;
            *(unsigned*)(VL + r * 72 + c)     = lA;
            *(unsigned*)(VL + r * 72 + c + 2) = lB;
        }
        __syncthreads();

        // ---- S = Q K^T (3-term bf16) ----
        float s[8][4];
        #pragma unroll
        for (int nt = 0; nt < 8; nt++)
            #pragma unroll
            for (int i = 0; i < 4; i++) s[nt][i] = 0.f;

        #pragma unroll
        for (int ks = 0; ks < 4; ks++) {
            const int k = ks * 16;
            #pragma unroll
            for (int nt = 0; nt < 8; nt++) {
                int n = nt * 8 + qr;
                unsigned bh[2], bl[2];
                bh[0] = *(const unsigned*)(KH + n * 72 + k + 2 * qc);
                bh[1] = *(const unsigned*)(KH + n * 72 + k + 8 + 2 * qc);
                bl[0] = *(const unsigned*)(KL + n * 72 + k + 2 * qc);
                bl[1] = *(const unsigned*)(KL + n * 72 + k + 8 + 2 * qc);
                mma_bf16(s[nt], qhi[ks], bh);
                mma_bf16(s[nt], qhi[ks], bl);
                mma_bf16(s[nt], qlo[ks], bh);
            }
        }
        __syncthreads();   // K reads done; KH/KL become PH/PL

        // ---- scale + causal mask + row max ----
        float mx0 = m0, mx1 = m1;
        #pragma unroll
        for (int nt = 0; nt < 8; nt++) {
            int cg = kj * 64 + nt * 8 + 2 * qc;
            #pragma unroll
            for (int d = 0; d < 2; d++) {
                float v0 = s[nt][d] * 0.125f;
                if (cg + d > rowg0) v0 = -1e30f;
                s[nt][d] = v0; mx0 = fmaxf(mx0, v0);
                float v1 = s[nt][2 + d] * 0.125f;
                if (cg + d > rowg1) v1 = -1e30f;
                s[nt][2 + d] = v1; mx1 = fmaxf(mx1, v1);
            }
        }
        mx0 = fmaxf(mx0, __shfl_xor_sync(0xffffffffu, mx0, 1));
        mx0 = fmaxf(mx0, __shfl_xor_sync(0xffffffffu, mx0, 2));
        mx1 = fmaxf(mx1, __shfl_xor_sync(0xffffffffu, mx1, 1));
        mx1 = fmaxf(mx1, __shfl_xor_sync(0xffffffffu, mx1, 2));

        float a0 = __expf(m0 - mx0);
        float a1 = __expf(m1 - mx1);
        m0 = mx0; m1 = mx1;

        float rs0 = 0.f, rs1 = 0.f;
        #pragma unroll
        for (int nt = 0; nt < 8; nt++) {
            float p0 = __expf(s[nt][0] - mx0), p1 = __expf(s[nt][1] - mx0);
            float p2 = __expf(s[nt][2] - mx1), p3 = __expf(s[nt][3] - mx1);
            rs0 += p0 + p1; rs1 += p2 + p3;
            unsigned hh, ll;
            bfsplit2(p0, p1, hh, ll);
            *(unsigned*)(KH + rm * 72 + nt * 8 + 2 * qc) = hh;   // PH
            *(unsigned*)(KL + rm * 72 + nt * 8 + 2 * qc) = ll;   // PL
            bfsplit2(p2, p3, hh, ll);
            *(unsigned*)(KH + (rm + 8) * 72 + nt * 8 + 2 * qc) = hh;
            *(unsigned*)(KL + (rm + 8) * 72 + nt * 8 + 2 * qc) = ll;
        }
        rs0 += __shfl_xor_sync(0xffffffffu, rs0, 1);
        rs0 += __shfl_xor_sync(0xffffffffu, rs0, 2);
        rs1 += __shfl_xor_sync(0xffffffffu, rs1, 1);
        rs1 += __shfl_xor_sync(0xffffffffu, rs1, 2);
        l0 = l0 * a0 + rs0;
        l1 = l1 * a1 + rs1;

        #pragma unroll
        for (int nt = 0; nt < 8; nt++) {
            o[nt][0] *= a0; o[nt][1] *= a0;
            o[nt][2] *= a1; o[nt][3] *= a1;
        }
        __syncthreads();   // P visible to all warps

        // ---- O += P V (3-term bf16, V B-frags via ldmatrix.trans) ----
        #pragma unroll
        for (int ks = 0; ks < 4; ks++) {
            const int k = ks * 16;
            unsigned ah[4], al[4];
            ah[0] = *(const unsigned*)(KH + rm * 72 + k + 2 * qc);
            ah[1] = *(const unsigned*)(KH + (rm + 8) * 72 + k + 2 * qc);
            ah[2] = *(const unsigned*)(KH + rm * 72 + k + 8 + 2 * qc);
            ah[3] = *(const unsigned*)(KH + (rm + 8) * 72 + k + 8 + 2 * qc);
            al[0] = *(const unsigned*)(KL + rm * 72 + k + 2 * qc);
            al[1] = *(const unsigned*)(KL + (rm + 8) * 72 + k + 2 * qc);
            al[2] = *(const unsigned*)(KL + rm * 72 + k + 8 + 2 * qc);
            al[3] = *(const unsigned*)(KL + (rm + 8) * 72 + k + 8 + 2 * qc);
            const uint32_t rowOff = (uint32_t)((k + l15) * 72) * 2u;
            #pragma unroll
            for (int nt = 0; nt < 8; nt++) {
                unsigned bh[2], bl[2];
                ldmx2t(bh[0], bh[1], vhb + rowOff + (uint32_t)(nt * 8) * 2u);
                ldmx2t(bl[0], bl[1], vlb + rowOff + (uint32_t)(nt * 8) * 2u);
                mma_bf16(o[nt], ah, bh);
                mma_bf16(o[nt], ah, bl);
                mma_bf16(o[nt], al, bh);
            }
        }
        __syncthreads();   // reads done before next tile staging
    }

    // ---- normalize + write ----
    float inv0 = 1.0f / l0, inv1 = 1.0f / l1;
    float* op = O + rowQ0 * DMODEL + headOff;
    #pragma unroll
    for (int nt = 0; nt < 8; nt++) {
        int c = nt * 8 + 2 * qc;
        *(float2*)(op + (size_t)rm * DMODEL + c)       = make_float2(o[nt][0] * inv0, o[nt][1] * inv0);
        *(float2*)(op + (size_t)(rm + 8) * DMODEL + c) = make_float2(o[nt][2] * inv1, o[nt][3] * inv1);
    }
}

// ---------------------------------------------------------------------------
// Launch
// ---------------------------------------------------------------------------
extern "C" void kernel_launch(void* const* d_in, const int* in_sizes, int n_in,
                              void* d_out, int out_size)
{
    const float* hidden = (const float*)d_in[0];
    const float* cosT   = (const float*)d_in[1];
    const float* sinT   = (const float*)d_in[2];
    // d_in[3] = attention_mask (pure causal; reproduced analytically)
    const float* Wq     = (const float*)d_in[4];
    const float* Wk     = (const float*)d_in[5];
    const float* Wv     = (const float*)d_in[6];
    const float* Wo     = (const float*)d_in[7];
    float* out = (float*)d_out;

    float *Qp, *Kp, *Vp, *Op;
    cudaGetSymbolAddress((void**)&Qp, g_Q);
    cudaGetSymbolAddress((void**)&Kp, g_K);
    cudaGetSymbolAddress((void**)&Vp, g_V);
    cudaGetSymbolAddress((void**)&Op, g_O);

    cudaFuncSetAttribute(gemm_tf32, cudaFuncAttributeMaxDynamicSharedMemorySize, GEMM_SMEM);
    cudaFuncSetAttribute(attn_mma,  cudaFuncAttributeMaxDynamicSharedMemorySize, ATTN_SMEM);

    dim3 gg(DMODEL / 128, MTOT / 128);   // (8, 32)

    gemm_tf32<<<gg, 256, GEMM_SMEM>>>(hidden, Wq, Qp, MTOT, DMODEL, DMODEL);
    gemm_tf32<<<gg, 256, GEMM_SMEM>>>(hidden, Wk, Kp, MTOT, DMODEL, DMODEL);
    gemm_tf32<<<gg, 256, GEMM_SMEM>>>(hidden, Wv, Vp, MTOT, DMODEL, DMODEL);

    rope_kernel<<<(MTOT * NHEADS * 32) / 256, 256>>>(Qp, Kp, cosT, sinT);

    attn_mma<<<dim3(SEQ / 64, NHEADS, BATCH), 128, ATTN_SMEM>>>(Qp, Kp, Vp, Op);

    gemm_tf32<<<gg, 256, GEMM_SMEM>>>(Op, Wo, out, MTOT, DMODEL, DMODEL);
}